// round 1
// baseline (speedup 1.0000x reference)
#include <cuda_runtime.h>

#define N_VOX 262144
#define HCH   64
#define KOFF  27
#define TILE_M 128
#define NTHREADS 128

// Intermediate activation: relu(conv_a(x)) — 64 MB device global (no allocs allowed).
__device__ float g_mid[N_VOX * HCH];

// Dynamic smem layout:
//   As   : [64][TILE_M] floats (A tile, transposed: As[kk][m])   = 32768 B
//   Bs   : [64][64]     floats (W[k], [in][out])                 = 16384 B
//   nbrS : [TILE_M][27] ints                                     = 13824 B
#define SMEM_BYTES (64 * TILE_M * 4 + 64 * HCH * 4 + TILE_M * KOFF * 4)

__global__ void __launch_bounds__(NTHREADS)
spconv_kernel(const float* __restrict__ feats,
              const float* __restrict__ W,
              const int*   __restrict__ nbr,
              const float* __restrict__ resid,   // nullptr if none
              float*       __restrict__ out,
              int do_relu)
{
    extern __shared__ float smem[];
    float* As   = smem;                          // 64 * TILE_M
    float* Bs   = smem + 64 * TILE_M;            // 64 * 64
    int*   nbrS = (int*)(Bs + 64 * HCH);         // TILE_M * 27

    const int row0 = blockIdx.x * TILE_M;
    const int t    = threadIdx.x;
    const int tx   = t & 7;    // col group: cols tx*8 .. tx*8+7
    const int ty   = t >> 3;   // row group: rows ty*8 .. ty*8+7  (16 groups * 8 = 128)

    // Cache this tile's neighbor indices (coalesced).
    for (int i = t; i < TILE_M * KOFF; i += NTHREADS)
        nbrS[i] = nbr[row0 * KOFF + i];

    float acc[8][8];
#pragma unroll
    for (int r = 0; r < 8; ++r)
#pragma unroll
        for (int c = 0; c < 8; ++c) acc[r][c] = 0.0f;

    __syncthreads();

    for (int k = 0; k < KOFF; ++k) {
        // Stage W[k] (64x64) into smem, coalesced float4 copy.
        {
            const float4* Wv = (const float4*)(W + k * HCH * HCH);
            float4* Bv = (float4*)Bs;
#pragma unroll
            for (int i = t; i < HCH * HCH / 4; i += NTHREADS)
                Bv[i] = Wv[i];
        }
        // Gather 128 neighbor rows into As, stored transposed As[kk][m].
        // 2048 float4 loads; 16 consecutive threads cover one 256B row (coalesced).
        for (int i = t; i < TILE_M * 16; i += NTHREADS) {
            const int m  = i >> 4;          // row within tile
            const int c4 = i & 15;          // float4 index within row
            const int idx = nbrS[m * KOFF + k];
            float4 v;
            if (idx < N_VOX)
                v = ((const float4*)feats)[idx * 16 + c4];
            else
                v = make_float4(0.f, 0.f, 0.f, 0.f);
            const int kk = c4 * 4;
            As[(kk + 0) * TILE_M + m] = v.x;
            As[(kk + 1) * TILE_M + m] = v.y;
            As[(kk + 2) * TILE_M + m] = v.z;
            As[(kk + 3) * TILE_M + m] = v.w;
        }
        __syncthreads();

        // 128x64x64 GEMM fragment: acc += As^T * Bs
#pragma unroll 4
        for (int kk = 0; kk < 64; ++kk) {
            const float4 a0 = *(const float4*)&As[kk * TILE_M + ty * 8];
            const float4 a1 = *(const float4*)&As[kk * TILE_M + ty * 8 + 4];
            const float4 b0 = *(const float4*)&Bs[kk * HCH + tx * 8];
            const float4 b1 = *(const float4*)&Bs[kk * HCH + tx * 8 + 4];
            const float a[8] = {a0.x, a0.y, a0.z, a0.w, a1.x, a1.y, a1.z, a1.w};
            const float b[8] = {b0.x, b0.y, b0.z, b0.w, b1.x, b1.y, b1.z, b1.w};
#pragma unroll
            for (int r = 0; r < 8; ++r)
#pragma unroll
                for (int c = 0; c < 8; ++c)
                    acc[r][c] = fmaf(a[r], b[c], acc[r][c]);
        }
        __syncthreads();
    }

    // Epilogue: optional ReLU, optional residual add, store.
#pragma unroll
    for (int r = 0; r < 8; ++r) {
        const int row = row0 + ty * 8 + r;
        float* orow = out + row * HCH + tx * 8;
        float v[8];
#pragma unroll
        for (int c = 0; c < 8; ++c) v[c] = acc[r][c];
        if (do_relu) {
#pragma unroll
            for (int c = 0; c < 8; ++c) v[c] = fmaxf(v[c], 0.0f);
        }
        if (resid != nullptr) {
            const float4 r0 = *(const float4*)(resid + row * HCH + tx * 8);
            const float4 r1 = *(const float4*)(resid + row * HCH + tx * 8 + 4);
            v[0] += r0.x; v[1] += r0.y; v[2] += r0.z; v[3] += r0.w;
            v[4] += r1.x; v[5] += r1.y; v[6] += r1.z; v[7] += r1.w;
        }
        float4 o0 = make_float4(v[0], v[1], v[2], v[3]);
        float4 o1 = make_float4(v[4], v[5], v[6], v[7]);
        *(float4*)(orow)     = o0;
        *(float4*)(orow + 4) = o1;
    }
}

extern "C" void kernel_launch(void* const* d_in, const int* in_sizes, int n_in,
                              void* d_out, int out_size)
{
    const float* x   = (const float*)d_in[0];   // [N, 64]
    const float* Wa  = (const float*)d_in[1];   // [27, 64, 64]
    const float* Wb  = (const float*)d_in[2];   // [27, 64, 64]
    const int*   nbr = (const int*)d_in[3];     // [N, 27]
    float* out = (float*)d_out;

    float* mid = nullptr;
    cudaGetSymbolAddress((void**)&mid, g_mid);

    static int smem_set = 0;
    if (!smem_set) {
        cudaFuncSetAttribute(spconv_kernel,
                             cudaFuncAttributeMaxDynamicSharedMemorySize,
                             SMEM_BYTES);
        smem_set = 1;
    }

    const int grid = N_VOX / TILE_M;   // 2048

    // conv_a + ReLU -> g_mid
    spconv_kernel<<<grid, NTHREADS, SMEM_BYTES>>>(x, Wa, nbr, nullptr, mid, 1);
    // conv_b + residual -> out
    spconv_kernel<<<grid, NTHREADS, SMEM_BYTES>>>(mid, Wb, nbr, x, out, 0);
}

// round 6
// speedup vs baseline: 3.9368x; 3.9368x over previous
#include <cuda_runtime.h>
#include <cuda_bf16.h>
#include <cstdint>

#define N_VOX 262144
#define HCH   64
#define KOFF  27
#define TILE_M 128
#define NT     128

#define WROW     72                    // padded W^T row: 72 bf16 = 144 B
#define WTILE_EL (HCH * WROW)          // 4608 elems per split tile
#define WTILE_B  (WTILE_EL * 2)        // 9216 B
#define WOFF_B   (2 * WTILE_B)         // 18432 B per offset (hi + lo)

// ---------------- device globals (no allocs allowed) ----------------
__device__ float g_mid[(size_t)N_VOX * HCH];
__device__ __align__(16) __nv_bfloat16 g_Wt[2][KOFF][2][WTILE_EL];

// ---------------- helpers ----------------
__device__ __forceinline__ uint32_t smem_u32(const void* p) {
    return (uint32_t)__cvta_generic_to_shared(p);
}
__device__ __forceinline__ void cp_async16(uint32_t dst, const void* src) {
    asm volatile("cp.async.ca.shared.global [%0], [%1], 16;" :: "r"(dst), "l"(src));
}
__device__ __forceinline__ void cp_commit() { asm volatile("cp.async.commit_group;"); }
__device__ __forceinline__ void cp_wait0()  { asm volatile("cp.async.wait_group 0;"); }

__device__ __forceinline__ void ldmx4(uint32_t* r, uint32_t addr) {
    asm volatile("ldmatrix.sync.aligned.m8n8.x4.shared.b16 {%0,%1,%2,%3}, [%4];"
                 : "=r"(r[0]), "=r"(r[1]), "=r"(r[2]), "=r"(r[3]) : "r"(addr));
}
__device__ __forceinline__ void mma16816(float* c, const uint32_t* a,
                                         uint32_t b0, uint32_t b1) {
    asm volatile("mma.sync.aligned.m16n8k16.row.col.f32.bf16.bf16.f32 "
                 "{%0,%1,%2,%3}, {%4,%5,%6,%7}, {%8,%9}, {%0,%1,%2,%3};"
                 : "+f"(c[0]), "+f"(c[1]), "+f"(c[2]), "+f"(c[3])
                 : "r"(a[0]), "r"(a[1]), "r"(a[2]), "r"(a[3]), "r"(b0), "r"(b1));
}

// ---------------- W prep: W[k][kin][n] -> W^T[n][kin], hi/lo split, 144B rows
__global__ void prep_w(const float* __restrict__ Wa, const float* __restrict__ Wb) {
    int i = blockIdx.x * blockDim.x + threadIdx.x;
    const int total = KOFF * HCH * HCH;
    if (i >= 2 * total) return;
    const int w = i / total;
    const int r = i - w * total;           // k*4096 + kin*64 + n
    const float v = (w == 0) ? Wa[r] : Wb[r];
    const int k   = r >> 12;
    const int kin = (r >> 6) & 63;
    const int n   = r & 63;
    __nv_bfloat16 hi = __float2bfloat16(v);
    __nv_bfloat16 lo = __float2bfloat16(v - __bfloat162float(hi));
    g_Wt[w][k][0][n * WROW + kin] = hi;
    g_Wt[w][k][1][n * WROW + kin] = lo;
}

// ---------------- main conv kernel (HMMA mma.sync) ----------------
__global__ void __launch_bounds__(NT, 3)
spconv_mma(const float* __restrict__ feats,
           const __nv_bfloat16* __restrict__ wt,    // [KOFF][2][WTILE_EL]
           const int* __restrict__ nbr,
           const float* __restrict__ resid,         // may be nullptr
           float* __restrict__ out,
           int do_relu)
{
    __shared__ __align__(16) char wbuf[2][WOFF_B];

    const int t    = threadIdx.x;
    const int w    = t >> 5;
    const int lane = t & 31;
    const int row0 = blockIdx.x * TILE_M;
    const int gr   = row0 + 32 * w + (lane >> 2);   // fragment base row (t=0)

    const uint32_t sb[2] = { smem_u32(wbuf[0]), smem_u32(wbuf[1]) };
    const int q = lane >> 3, e = lane & 7;
    const uint32_t lm_lane = (uint32_t)(((q & 1) * 8 + e) * 144 + (q >> 1) * 16);

    float acc[2][8][4];
#pragma unroll
    for (int a = 0; a < 2; ++a)
#pragma unroll
        for (int j = 0; j < 8; ++j)
#pragma unroll
            for (int c = 0; c < 4; ++c) acc[a][j][c] = 0.0f;

    // ---- idx loader: rows gr, gr+8 (m-tile 0), gr+16, gr+24 (m-tile 1)
    int idxc[4], idxn[4];
#define LOAD_IDX(dst, kk) do { \
        dst[0] = __ldg(&nbr[(size_t)(gr)      * KOFF + (kk)]); \
        dst[1] = __ldg(&nbr[(size_t)(gr + 8)  * KOFF + (kk)]); \
        dst[2] = __ldg(&nbr[(size_t)(gr + 16) * KOFF + (kk)]); \
        dst[3] = __ldg(&nbr[(size_t)(gr + 24) * KOFF + (kk)]); } while (0)

    // ---- A fragment gmem loads: 8 float2 (2 m-tiles x {rowlo,rowhi} x {klo,khi})
    float2 nA[8];
#define LOAD_A(dst, idx, kc) do { \
        const int cb = (kc) * 16 + (lane & 3) * 2; \
        _Pragma("unroll") \
        for (int tt = 0; tt < 2; ++tt) { \
            _Pragma("unroll") \
            for (int h = 0; h < 2; ++h) { \
                const int id = idx[tt * 2 + h]; \
                float2 v0 = make_float2(0.f, 0.f), v1 = v0; \
                if (id < N_VOX) { \
                    const float2* p = (const float2*)(feats + (size_t)id * HCH + cb); \
                    v0 = p[0]; v1 = p[4]; \
                } \
                dst[tt * 4 + h]     = v0; \
                dst[tt * 4 + 2 + h] = v1; \
            } \
        } } while (0)

    // ---- prologue: stage W[0], prefetch idx + A(k=0,kc=0)
    {
        const char* src = (const char*)wt;
        for (int i = t; i < WOFF_B / 16; i += NT)
            cp_async16(sb[0] + i * 16, src + i * 16);
        cp_commit();
    }
    LOAD_IDX(idxc, 0);
    LOAD_A(nA, idxc, 0);
    cp_wait0();
    __syncthreads();

#pragma unroll 1
    for (int k = 0; k < KOFF; ++k) {
        const int b = k & 1;
        if (k < KOFF - 1) {
            const char* src = (const char*)wt + (size_t)(k + 1) * WOFF_B;
            for (int i = t; i < WOFF_B / 16; i += NT)
                cp_async16(sb[b ^ 1] + i * 16, src + i * 16);
            cp_commit();
            LOAD_IDX(idxn, k + 1);
        }
        const uint32_t sbuf = sb[b];

#pragma unroll
        for (int kc = 0; kc < 4; ++kc) {
            // convert current A to bf16 hi/lo fragments (frees nA)
            uint32_t Ah[2][4], Al[2][4];
#pragma unroll
            for (int i = 0; i < 8; ++i) {
                const float2 v = nA[i];
                __nv_bfloat162 h = __floats2bfloat162_rn(v.x, v.y);
                const float lx = v.x - __bfloat162float(h.x);
                const float ly = v.y - __bfloat162float(h.y);
                __nv_bfloat162 l = __floats2bfloat162_rn(lx, ly);
                Ah[i >> 2][i & 3] = *(uint32_t*)&h;
                Al[i >> 2][i & 3] = *(uint32_t*)&l;
            }
            // prefetch next A chunk
            if (kc < 3)               { LOAD_A(nA, idxc, kc + 1); }
            else if (k < KOFF - 1)    { LOAD_A(nA, idxn, 0); }

            // ldmatrix B hi/lo fragments for this k-chunk
            uint32_t bh[16], bl[16];
#pragma unroll
            for (int u = 0; u < 4; ++u) {
                const uint32_t a0 = sbuf + (uint32_t)(u * 16 * 144 + kc * 32) + lm_lane;
                ldmx4(&bh[u * 4], a0);
                ldmx4(&bl[u * 4], a0 + WTILE_B);
            }

            // 48 MMAs: 2 m-tiles x 8 n-tiles x 3 combos
#pragma unroll
            for (int tt = 0; tt < 2; ++tt) {
#pragma unroll
                for (int j = 0; j < 8; ++j) {
                    const int u4 = (j >> 1) * 4 + (j & 1);
                    mma16816(acc[tt][j], Ah[tt], bh[u4], bh[u4 + 2]);
                    mma16816(acc[tt][j], Ah[tt], bl[u4], bl[u4 + 2]);
                    mma16816(acc[tt][j], Al[tt], bh[u4], bh[u4 + 2]);
                }
            }
        }

        if (k < KOFF - 1) cp_wait0();
        __syncthreads();
        idxc[0] = idxn[0]; idxc[1] = idxn[1];
        idxc[2] = idxn[2]; idxc[3] = idxn[3];
    }

    // ---- epilogue: relu / residual, float2 stores
#pragma unroll
    for (int tt = 0; tt < 2; ++tt) {
        const int r0 = gr + 16 * tt;
#pragma unroll
        for (int half = 0; half < 2; ++half) {
            const int row = r0 + 8 * half;
#pragma unroll
            for (int j = 0; j < 8; ++j) {
                const int c = j * 8 + (lane & 3) * 2;
                float v0 = acc[tt][j][half * 2 + 0];
                float v1 = acc[tt][j][half * 2 + 1];
                if (do_relu) { v0 = fmaxf(v0, 0.f); v1 = fmaxf(v1, 0.f); }
                if (resid) {
                    const float2 r = *(const float2*)(resid + (size_t)row * HCH + c);
                    v0 += r.x; v1 += r.y;
                }
                *(float2*)(out + (size_t)row * HCH + c) = make_float2(v0, v1);
            }
        }
    }
}

// ---------------- launch ----------------
extern "C" void kernel_launch(void* const* d_in, const int* in_sizes, int n_in,
                              void* d_out, int out_size)
{
    const float* x   = (const float*)d_in[0];   // [N, 64]
    const float* Wa  = (const float*)d_in[1];   // [27, 64, 64]
    const float* Wb  = (const float*)d_in[2];   // [27, 64, 64]
    const int*   nbr = (const int*)d_in[3];     // [N, 27]
    float* out = (float*)d_out;

    float* mid = nullptr;
    __nv_bfloat16* wt = nullptr;
    cudaGetSymbolAddress((void**)&mid, g_mid);
    cudaGetSymbolAddress((void**)&wt, g_Wt);

    const int total = 2 * KOFF * HCH * HCH;
    prep_w<<<(total + 255) / 256, 256>>>(Wa, Wb);

    const int grid = N_VOX / TILE_M;   // 2048
    const size_t wstride = (size_t)KOFF * 2 * WTILE_EL;
    // conv_a + ReLU -> g_mid
    spconv_mma<<<grid, NT>>>(x, wt, nbr, nullptr, mid, 1);
    // conv_b + residual -> out
    spconv_mma<<<grid, NT>>>(mid, wt + wstride, nbr, x, out, 0);
}